// round 14
// baseline (speedup 1.0000x reference)
#include <cuda_runtime.h>
#include <math.h>

#define N_TOT   4096
#define N_UP    2048
#define HIDDEN  32
#define BOX     10.0f
#define TBL     4096
#define SMAX    25.0f        // r_cut^2 = 5^2
#define CHUNK   64
#define THREADS 256          // main kernel CTA size (rows per CTA)
#define BTHREADS 256         // build kernel CTA size
#define INIT_CTAS 16

#define MAGIC     12582912.0f        // 1.5 * 2^23
#define BASEBITS  0x4B400000u        // float bits of MAGIC
#define CAPBITS   (BASEBITS + (TBL - 1))

typedef unsigned long long u64;

// ---- packed f32x2 helpers (sm_103a; ptxas never emits these from C++) ----
__device__ __forceinline__ u64 pk2(float lo, float hi) {
    u64 r; asm("mov.b64 %0,{%1,%2};" : "=l"(r) : "f"(lo), "f"(hi)); return r;
}
__device__ __forceinline__ void upk2u(u64 v, unsigned& lo, unsigned& hi) {
    asm("mov.b64 {%0,%1},%2;" : "=r"(lo), "=r"(hi) : "l"(v));
}
__device__ __forceinline__ void upk2(u64 v, float& lo, float& hi) {
    asm("mov.b64 {%0,%1},%2;" : "=f"(lo), "=f"(hi) : "l"(v));
}
__device__ __forceinline__ u64 add2(u64 a, u64 b) {
    u64 r; asm("add.rn.f32x2 %0,%1,%2;" : "=l"(r) : "l"(a), "l"(b)); return r;
}
__device__ __forceinline__ u64 mul2(u64 a, u64 b) {
    u64 r; asm("mul.rn.f32x2 %0,%1,%2;" : "=l"(r) : "l"(a), "l"(b)); return r;
}
__device__ __forceinline__ u64 fma2(u64 a, u64 b, u64 c) {
    u64 r; asm("fma.rn.f32x2 %0,%1,%2,%3;" : "=l"(r) : "l"(a), "l"(b), "l"(c)); return r;
}

__device__ __forceinline__ unsigned smem_u32(const void* p) {
    unsigned a;
    asm("{ .reg .u64 t; cvta.to.shared.u64 t, %1; cvt.u32.u64 %0, t; }"
        : "=r"(a) : "l"(p));
    return a;
}

// Precomputed f(s) tables (values pre-divided by coord scale cs).
// Nearest-neighbor lookup: plain float entries. [0]=same, [1]=diff.
__device__ __align__(16) float g_tab[2][TBL];

// ---------------------------------------------------------------------------
// MUFU fast paths (__expf/__fdividef): ~2 ulp error, invisible under the
// table's 3e-4 quantization budget; shortens the builder's latency chain.
__device__ __forceinline__ float decay_of_s(float s) {
    float r  = sqrtf(s + 1e-15f);
    float xn = fminf(r * (1.0f / 5.0f), 1.0f - 1e-5f);
    float u  = 1.0f - xn * xn;
    return __expf(1.0f - __fdividef(1.0f, u));
}
__device__ __forceinline__ float unit_contrib(float decay, float w1, float b1, float wo) {
    float z = fmaf(decay, w1, b1);
    float h = __fdividef(z, 1.0f + __expf(-z));
    return h * wo;
}

// Fused: build tables (warp per entry, lane per hidden unit) + out=rs init.
// PDL completion triggers at CTA END (R12 showed early trigger floods SMs).
__global__ void __launch_bounds__(BTHREADS)
build_and_init(const float* __restrict__ rs, float* __restrict__ out,
               const float* __restrict__ sw1, const float* __restrict__ sb1,
               const float* __restrict__ swo, const float* __restrict__ sbo,
               const float* __restrict__ dw1, const float* __restrict__ db1,
               const float* __restrict__ dwo, const float* __restrict__ dbo) {
    const int bid = blockIdx.x;
    const int tid = threadIdx.x;

    if (bid < INIT_CTAS) {
        for (int i = bid * BTHREADS + tid; i < N_TOT * 3; i += INIT_CTAS * BTHREADS)
            out[i] = rs[i];
        cudaTriggerProgrammaticLaunchCompletion();
        return;
    }

    const int wglob = (bid - INIT_CTAS) * (BTHREADS / 32) + (tid >> 5);
    if (wglob < 2 * TBL) {
        const int net  = wglob / TBL;
        const int k    = wglob % TBL;
        const int lane = tid & 31;

        const float w1 = net ? dw1[lane] : sw1[lane];
        const float b1 = net ? db1[lane] : sb1[lane];
        const float wo = net ? dwo[lane] : swo[lane];
        const float bo = net ? dbo[0]    : sbo[0];

        const float h = SMAX / (float)(TBL - 1);
        const float d0 = decay_of_s((float)k * h);

        float a0 = unit_contrib(d0, w1, b1, wo);
        #pragma unroll
        for (int off = 16; off > 0; off >>= 1)
            a0 += __shfl_xor_sync(0xFFFFFFFFu, a0, off);
        if (lane == 0) {
            const float cs = sqrtf((float)(TBL - 1) / SMAX);   // coord scale
            g_tab[net][k] = (a0 + bo) * d0 / cs;
        }
    }
    cudaTriggerProgrammaticLaunchCompletion();
}

// ---------------------------------------------------------------------------
// Main pairwise kernel: grid (16 x 64) = 1024 CTAs, 256 threads.
// PDL secondary: prologue (ramp, mbarrier init, j staging, i loads — reads
// only rs) overlaps the builder tail; cudaGridDependencySynchronize() before
// the TMA reads g_tab / atomics touch out. Table staged via cp.async.bulk.
// Coordinates pre-scaled so t = |d'|^2 is the table coordinate (nearest).
// Two j's per iteration via f32x2 packing.
// ---------------------------------------------------------------------------
__global__ void __launch_bounds__(THREADS)
backflow_kernel(const float* __restrict__ rs, float* __restrict__ out) {
    __shared__ __align__(16) float s_tab[TBL];             // 16 KB
    __shared__ __align__(16) float sjx[CHUNK];             // NEGATED, scaled j coords
    __shared__ __align__(16) float sjy[CHUNK];
    __shared__ __align__(16) float sjz[CHUNK];
    __shared__ __align__(8)  u64   s_mbar;

    const int tid    = threadIdx.x;
    const int rowBlk = blockIdx.x;       // 0..15 (256 rows each)
    const int jBlk   = blockIdx.y;       // 0..63 (64 cols each)
    const int i      = rowBlk * THREADS + tid;
    const int j0     = jBlk * CHUNK;

    const int net = ((rowBlk < 8) == (jBlk < 32)) ? 0 : 1;

    const float cs   = sqrtf((float)(TBL - 1) / SMAX);   // coord scale
    const float BOXS = BOX * cs;

    const unsigned mbar = smem_u32(&s_mbar);
    if (tid == 0) {
        asm volatile("mbarrier.init.shared.b64 [%0], 1;" :: "r"(mbar) : "memory");
        asm volatile("fence.proxy.async.shared::cta;" ::: "memory");
    }

    // stage this chunk's j coordinates (reads only rs — safe pre-sync)
    if (tid < CHUNK) {
        int j = j0 + tid;
        sjx[tid] = -cs * rs[3 * j + 0];
        sjy[tid] = -cs * rs[3 * j + 1];
        sjz[tid] = -cs * rs[3 * j + 2];
    }

    // i coordinates (reads only rs — safe pre-sync)
    const float xi = cs * rs[3 * i + 0];
    const float yi = cs * rs[3 * i + 1];
    const float zi = cs * rs[3 * i + 2];

    __syncthreads();   // mbarrier.init + sj stores visible

    // wait for the builder grid (table + out=rs init) before touching g_tab/out
    cudaGridDependencySynchronize();

    if (tid == 0) {
        asm volatile("mbarrier.arrive.expect_tx.shared.b64 _, [%0], %1;"
                     :: "r"(mbar), "r"((unsigned)(TBL * 4)) : "memory");
        asm volatile(
            "cp.async.bulk.shared::cluster.global.mbarrier::complete_tx::bytes "
            "[%0], [%1], %2, [%3];"
            :: "r"(smem_u32(s_tab)), "l"(&g_tab[net][0]),
               "r"((unsigned)(TBL * 4)), "r"(mbar) : "memory");
    }

    // wait for TMA completion (parity 0)
    {
        unsigned done;
        asm volatile(
            "{ .reg .pred p;\n"
            "  mbarrier.try_wait.parity.acquire.cta.shared::cta.b64 p, [%1], 0;\n"
            "  selp.b32 %0, 1, 0, p; }"
            : "=r"(done) : "r"(mbar) : "memory");
        if (!done) {
            asm volatile(
                "{ .reg .pred P1;\n"
                "WAIT_%=:\n"
                "  mbarrier.try_wait.parity.acquire.cta.shared::cta.b64 P1, [%0], 0, 0x989680;\n"
                "  @P1 bra.uni DONE_%=;\n"
                "  bra.uni WAIT_%=;\n"
                "DONE_%=:\n}"
                :: "r"(mbar) : "memory");
        }
    }

    const u64 xi2 = pk2(xi, xi);
    const u64 yi2 = pk2(yi, yi);
    const u64 zi2 = pk2(zi, zi);

    const u64 c_invb = pk2(1.0f / BOXS, 1.0f / BOXS);
    const u64 c_mag  = pk2(MAGIC, MAGIC);
    const u64 c_nmag = pk2(-MAGIC, -MAGIC);
    const u64 c_nb   = pk2(-BOXS, -BOXS);

    u64 ax2 = 0, ay2 = 0, az2 = 0;   // packed (0.0f, 0.0f)

    #pragma unroll 8
    for (int c = 0; c < CHUNK / 2; c++) {
        const u64 nx = *(const u64*)&sjx[2 * c];   // broadcast LDS.64
        const u64 ny = *(const u64*)&sjy[2 * c];
        const u64 nz = *(const u64*)&sjz[2 * c];

        u64 dx = add2(xi2, nx);
        u64 dy = add2(yi2, ny);
        u64 dz = add2(zi2, nz);

        // min image (scaled box): d -= BOXS * round(d/BOXS) via magic constant
        u64 mx = fma2(dx, c_invb, c_mag);
        u64 my = fma2(dy, c_invb, c_mag);
        u64 mz = fma2(dz, c_invb, c_mag);
        dx = fma2(add2(mx, c_nmag), c_nb, dx);
        dy = fma2(add2(my, c_nmag), c_nb, dy);
        dz = fma2(add2(mz, c_nmag), c_nb, dz);

        // t = |d'|^2 is the table coordinate; nearest index via magic bits
        u64 t2 = fma2(dx, dx, fma2(dy, dy, mul2(dz, dz)));
        u64 m2 = add2(t2, c_mag);

        unsigned kb0, kb1;
        upk2u(m2, kb0, kb1);
        kb0 = min(kb0, CAPBITS);
        kb1 = min(kb1, CAPBITS);

        float f0 = s_tab[kb0 - BASEBITS];
        float f1 = s_tab[kb1 - BASEBITS];

        const u64 f2 = pk2(f0, f1);
        ax2 = fma2(f2, dx, ax2);
        ay2 = fma2(f2, dy, ay2);
        az2 = fma2(f2, dz, az2);
    }

    float axl, axh, ayl, ayh, azl, azh;
    upk2(ax2, axl, axh);
    upk2(ay2, ayl, ayh);
    upk2(az2, azl, azh);

    atomicAdd(&out[3 * i + 0], axl + axh);
    atomicAdd(&out[3 * i + 1], ayl + ayh);
    atomicAdd(&out[3 * i + 2], azl + azh);
}

extern "C" void kernel_launch(void* const* d_in, const int* in_sizes, int n_in,
                              void* d_out, int out_size) {
    const float* rs  = (const float*)d_in[0];
    const float* sw1 = (const float*)d_in[1];
    const float* sb1 = (const float*)d_in[2];
    const float* swo = (const float*)d_in[3];
    const float* sbo = (const float*)d_in[4];
    const float* dw1 = (const float*)d_in[5];
    const float* db1 = (const float*)d_in[6];
    const float* dwo = (const float*)d_in[7];
    const float* dbo = (const float*)d_in[8];
    float* out = (float*)d_out;

    const int buildGrid = INIT_CTAS + (2 * TBL) / (BTHREADS / 32);
    build_and_init<<<buildGrid, BTHREADS>>>(rs, out,
                                            sw1, sb1, swo, sbo,
                                            dw1, db1, dwo, dbo);

    // backflow with programmatic dependent launch (overlap with builder tail)
    cudaLaunchConfig_t cfg = {};
    cfg.gridDim  = dim3(N_TOT / THREADS, N_TOT / CHUNK, 1);   // (16, 64)
    cfg.blockDim = dim3(THREADS, 1, 1);
    cfg.dynamicSmemBytes = 0;
    cfg.stream = (cudaStream_t)0;   // legacy default stream (captured by harness)

    cudaLaunchAttribute attrs[1];
    attrs[0].id = cudaLaunchAttributeProgrammaticStreamSerialization;
    attrs[0].val.programmaticStreamSerializationAllowed = 1;
    cfg.attrs = attrs;
    cfg.numAttrs = 1;

    cudaLaunchKernelEx(&cfg, backflow_kernel, rs, out);
}

// round 15
// speedup vs baseline: 1.3288x; 1.3288x over previous
#include <cuda_runtime.h>
#include <math.h>

#define N_TOT   4096
#define N_UP    2048
#define HIDDEN  32
#define BOX     10.0f
#define TBL     4096
#define SMAX    25.0f        // r_cut^2 = 5^2
#define CHUNK   64
#define THREADS 256          // main kernel CTA size (rows per CTA)
#define BTHREADS 256         // build kernel CTA size
#define INIT_CTAS 16

#define MAGIC     12582912.0f        // 1.5 * 2^23
#define BASEBITS  0x4B400000u        // float bits of MAGIC
#define CAPBITS   (BASEBITS + (TBL - 1))

typedef unsigned long long u64;

// ---- packed f32x2 helpers (sm_103a; ptxas never emits these from C++) ----
__device__ __forceinline__ u64 pk2(float lo, float hi) {
    u64 r; asm("mov.b64 %0,{%1,%2};" : "=l"(r) : "f"(lo), "f"(hi)); return r;
}
__device__ __forceinline__ void upk2u(u64 v, unsigned& lo, unsigned& hi) {
    asm("mov.b64 {%0,%1},%2;" : "=r"(lo), "=r"(hi) : "l"(v));
}
__device__ __forceinline__ void upk2(u64 v, float& lo, float& hi) {
    asm("mov.b64 {%0,%1},%2;" : "=f"(lo), "=f"(hi) : "l"(v));
}
__device__ __forceinline__ u64 add2(u64 a, u64 b) {
    u64 r; asm("add.rn.f32x2 %0,%1,%2;" : "=l"(r) : "l"(a), "l"(b)); return r;
}
__device__ __forceinline__ u64 mul2(u64 a, u64 b) {
    u64 r; asm("mul.rn.f32x2 %0,%1,%2;" : "=l"(r) : "l"(a), "l"(b)); return r;
}
__device__ __forceinline__ u64 fma2(u64 a, u64 b, u64 c) {
    u64 r; asm("fma.rn.f32x2 %0,%1,%2,%3;" : "=l"(r) : "l"(a), "l"(b), "l"(c)); return r;
}

__device__ __forceinline__ unsigned smem_u32(const void* p) {
    unsigned a;
    asm("{ .reg .u64 t; cvta.to.shared.u64 t, %1; cvt.u32.u64 %0, t; }"
        : "=r"(a) : "l"(p));
    return a;
}

// Precomputed f(s) tables (values pre-divided by coord scale cs).
// Nearest-neighbor lookup: plain float entries. [0]=same, [1]=diff.
__device__ __align__(16) float g_tab[2][TBL];

// ---------------------------------------------------------------------------
// MUFU fast paths: ~2 ulp, invisible under the table's 3e-4 budget.
__device__ __forceinline__ float decay_of_s(float s) {
    float r  = sqrtf(s + 1e-15f);
    float xn = fminf(r * (1.0f / 5.0f), 1.0f - 1e-5f);
    float u  = 1.0f - xn * xn;
    return __expf(1.0f - __fdividef(1.0f, u));
}
__device__ __forceinline__ float unit_contrib(float decay, float w1, float b1, float wo) {
    float z = fmaf(decay, w1, b1);
    float h = __fdividef(z, 1.0f + __expf(-z));
    return h * wo;
}

// Fused: build tables (warp per entry, lane per hidden unit) + out=rs init.
// PDL completion triggers at CTA END (early trigger floods SMs — R12).
__global__ void __launch_bounds__(BTHREADS)
build_and_init(const float* __restrict__ rs, float* __restrict__ out,
               const float* __restrict__ sw1, const float* __restrict__ sb1,
               const float* __restrict__ swo, const float* __restrict__ sbo,
               const float* __restrict__ dw1, const float* __restrict__ db1,
               const float* __restrict__ dwo, const float* __restrict__ dbo) {
    const int bid = blockIdx.x;
    const int tid = threadIdx.x;

    if (bid < INIT_CTAS) {
        for (int i = bid * BTHREADS + tid; i < N_TOT * 3; i += INIT_CTAS * BTHREADS)
            out[i] = rs[i];
        cudaTriggerProgrammaticLaunchCompletion();
        return;
    }

    const int wglob = (bid - INIT_CTAS) * (BTHREADS / 32) + (tid >> 5);
    if (wglob < 2 * TBL) {
        const int net  = wglob / TBL;
        const int k    = wglob % TBL;
        const int lane = tid & 31;

        const float w1 = net ? dw1[lane] : sw1[lane];
        const float b1 = net ? db1[lane] : sb1[lane];
        const float wo = net ? dwo[lane] : swo[lane];
        const float bo = net ? dbo[0]    : sbo[0];

        const float h = SMAX / (float)(TBL - 1);
        const float d0 = decay_of_s((float)k * h);

        float a0 = unit_contrib(d0, w1, b1, wo);
        #pragma unroll
        for (int off = 16; off > 0; off >>= 1)
            a0 += __shfl_xor_sync(0xFFFFFFFFu, a0, off);
        if (lane == 0) {
            const float cs = sqrtf((float)(TBL - 1) / SMAX);   // coord scale
            g_tab[net][k] = (a0 + bo) * d0 / cs;
        }
    }
    cudaTriggerProgrammaticLaunchCompletion();
}

// ---------------------------------------------------------------------------
// Main pairwise kernel: grid (16 x 64) = 1024 CTAs, 256 threads.
// Software-pipelined inner loop: table LDS for pair c issues a full
// iteration before its consumption, with pair c+1's distance math (13
// independent fma ops) filling the latency/replay window — overlapping the
// crossbar and fma pipes instead of running them back-to-back.
// ---------------------------------------------------------------------------
__global__ void __launch_bounds__(THREADS)
backflow_kernel(const float* __restrict__ rs, float* __restrict__ out) {
    __shared__ __align__(16) float s_tab[TBL];             // 16 KB
    __shared__ __align__(16) float sjx[CHUNK];             // NEGATED, scaled j coords
    __shared__ __align__(16) float sjy[CHUNK];
    __shared__ __align__(16) float sjz[CHUNK];
    __shared__ __align__(8)  u64   s_mbar;

    const int tid    = threadIdx.x;
    const int rowBlk = blockIdx.x;       // 0..15 (256 rows each)
    const int jBlk   = blockIdx.y;       // 0..63 (64 cols each)
    const int i      = rowBlk * THREADS + tid;
    const int j0     = jBlk * CHUNK;

    const int net = ((rowBlk < 8) == (jBlk < 32)) ? 0 : 1;

    const float cs   = sqrtf((float)(TBL - 1) / SMAX);   // coord scale
    const float BOXS = BOX * cs;

    const unsigned mbar = smem_u32(&s_mbar);
    if (tid == 0) {
        asm volatile("mbarrier.init.shared.b64 [%0], 1;" :: "r"(mbar) : "memory");
        asm volatile("fence.proxy.async.shared::cta;" ::: "memory");
    }

    // stage this chunk's j coordinates (reads only rs — safe pre-sync)
    if (tid < CHUNK) {
        int j = j0 + tid;
        sjx[tid] = -cs * rs[3 * j + 0];
        sjy[tid] = -cs * rs[3 * j + 1];
        sjz[tid] = -cs * rs[3 * j + 2];
    }

    // i coordinates (reads only rs — safe pre-sync)
    const float xi = cs * rs[3 * i + 0];
    const float yi = cs * rs[3 * i + 1];
    const float zi = cs * rs[3 * i + 2];

    __syncthreads();   // mbarrier.init + sj stores visible

    // wait for the builder grid (table + out=rs init) before touching g_tab/out
    cudaGridDependencySynchronize();

    if (tid == 0) {
        asm volatile("mbarrier.arrive.expect_tx.shared.b64 _, [%0], %1;"
                     :: "r"(mbar), "r"((unsigned)(TBL * 4)) : "memory");
        asm volatile(
            "cp.async.bulk.shared::cluster.global.mbarrier::complete_tx::bytes "
            "[%0], [%1], %2, [%3];"
            :: "r"(smem_u32(s_tab)), "l"(&g_tab[net][0]),
               "r"((unsigned)(TBL * 4)), "r"(mbar) : "memory");
    }

    // wait for TMA completion (parity 0)
    {
        unsigned done;
        asm volatile(
            "{ .reg .pred p;\n"
            "  mbarrier.try_wait.parity.acquire.cta.shared::cta.b64 p, [%1], 0;\n"
            "  selp.b32 %0, 1, 0, p; }"
            : "=r"(done) : "r"(mbar) : "memory");
        if (!done) {
            asm volatile(
                "{ .reg .pred P1;\n"
                "WAIT_%=:\n"
                "  mbarrier.try_wait.parity.acquire.cta.shared::cta.b64 P1, [%0], 0, 0x989680;\n"
                "  @P1 bra.uni DONE_%=;\n"
                "  bra.uni WAIT_%=;\n"
                "DONE_%=:\n}"
                :: "r"(mbar) : "memory");
        }
    }

    const u64 xi2 = pk2(xi, xi);
    const u64 yi2 = pk2(yi, yi);
    const u64 zi2 = pk2(zi, zi);

    const u64 c_invb = pk2(1.0f / BOXS, 1.0f / BOXS);
    const u64 c_mag  = pk2(MAGIC, MAGIC);
    const u64 c_nmag = pk2(-MAGIC, -MAGIC);
    const u64 c_nb   = pk2(-BOXS, -BOXS);

    u64 ax2 = 0, ay2 = 0, az2 = 0;   // packed (0.0f, 0.0f)

    // pair-compute: wrapped packed distances + clamped table-index bits
    auto compute_pair = [&](int c, u64& dx, u64& dy, u64& dz,
                            unsigned& k0, unsigned& k1) {
        const u64 nx = *(const u64*)&sjx[2 * c];   // broadcast LDS.64
        const u64 ny = *(const u64*)&sjy[2 * c];
        const u64 nz = *(const u64*)&sjz[2 * c];
        dx = add2(xi2, nx);
        dy = add2(yi2, ny);
        dz = add2(zi2, nz);
        u64 mx = fma2(dx, c_invb, c_mag);
        u64 my = fma2(dy, c_invb, c_mag);
        u64 mz = fma2(dz, c_invb, c_mag);
        dx = fma2(add2(mx, c_nmag), c_nb, dx);
        dy = fma2(add2(my, c_nmag), c_nb, dy);
        dz = fma2(add2(mz, c_nmag), c_nb, dz);
        u64 t2 = fma2(dx, dx, fma2(dy, dy, mul2(dz, dz)));
        u64 m2 = add2(t2, c_mag);
        upk2u(m2, k0, k1);
        k0 = min(k0, CAPBITS) - BASEBITS;
        k1 = min(k1, CAPBITS) - BASEBITS;
    };

    // software pipeline: lookup for pair c issues while pair c+1 computes
    u64 pdx, pdy, pdz;
    unsigned pk0, pk1;
    compute_pair(0, pdx, pdy, pdz, pk0, pk1);

    #pragma unroll
    for (int c = 0; c < CHUNK / 2; c++) {
        // issue table loads for the CURRENT pair (indices ready last iter)
        float f0 = s_tab[pk0];
        float f1 = s_tab[pk1];
        const u64 fdx = pdx, fdy = pdy, fdz = pdz;

        // overlap: compute NEXT pair's distances + indices (13 fma ops)
        if (c + 1 < CHUNK / 2)
            compute_pair(c + 1, pdx, pdy, pdz, pk0, pk1);

        // consume loads (a full compute block after issue)
        const u64 f2 = pk2(f0, f1);
        ax2 = fma2(f2, fdx, ax2);
        ay2 = fma2(f2, fdy, ay2);
        az2 = fma2(f2, fdz, az2);
    }

    float axl, axh, ayl, ayh, azl, azh;
    upk2(ax2, axl, axh);
    upk2(ay2, ayl, ayh);
    upk2(az2, azl, azh);

    atomicAdd(&out[3 * i + 0], axl + axh);
    atomicAdd(&out[3 * i + 1], ayl + ayh);
    atomicAdd(&out[3 * i + 2], azl + azh);
}

extern "C" void kernel_launch(void* const* d_in, const int* in_sizes, int n_in,
                              void* d_out, int out_size) {
    const float* rs  = (const float*)d_in[0];
    const float* sw1 = (const float*)d_in[1];
    const float* sb1 = (const float*)d_in[2];
    const float* swo = (const float*)d_in[3];
    const float* sbo = (const float*)d_in[4];
    const float* dw1 = (const float*)d_in[5];
    const float* db1 = (const float*)d_in[6];
    const float* dwo = (const float*)d_in[7];
    const float* dbo = (const float*)d_in[8];
    float* out = (float*)d_out;

    const int buildGrid = INIT_CTAS + (2 * TBL) / (BTHREADS / 32);
    build_and_init<<<buildGrid, BTHREADS>>>(rs, out,
                                            sw1, sb1, swo, sbo,
                                            dw1, db1, dwo, dbo);

    // backflow with programmatic dependent launch (overlap with builder tail)
    cudaLaunchConfig_t cfg = {};
    cfg.gridDim  = dim3(N_TOT / THREADS, N_TOT / CHUNK, 1);   // (16, 64)
    cfg.blockDim = dim3(THREADS, 1, 1);
    cfg.dynamicSmemBytes = 0;
    cfg.stream = (cudaStream_t)0;   // legacy default stream (captured by harness)

    cudaLaunchAttribute attrs[1];
    attrs[0].id = cudaLaunchAttributeProgrammaticStreamSerialization;
    attrs[0].val.programmaticStreamSerializationAllowed = 1;
    cfg.attrs = attrs;
    cfg.numAttrs = 1;

    cudaLaunchKernelEx(&cfg, backflow_kernel, rs, out);
}